// round 9
// baseline (speedup 1.0000x reference)
#include <cuda_runtime.h>
#include <cstdint>

// QNADE — autoregressive NADE. N=8192, D=64, H=4096, M=2.
// acc holds PRE-SCALED pre-activation: acc = 2*log2(e)*(b1 + sum_j x_j W1[j,:]).
// q = 1/(exp2(acc)+1)  (tanh = 1-2q);  z = C - 2*dot(q, W2col), C = sum(W2col)+b2.
// Two sites per phase: one barrier / reduction / leader region per 2 sites.

#define N_SAMP   8192
#define D_SITES  64
#define H_DIM    4096
#define B_SAMP   4
#define THREADS  512
#define HPART    128          // threads per sample
#define PER_THR  32           // h-elements per thread
#define PAD_CH   36           // 32 data + 4 pad words -> conflict-free LDS.128
#define CH       (HPART * PAD_CH)    // 4608 floats per W1 row buffer
#define KTANH    2.8853900817779268f // 2*log2(e)

typedef unsigned long long ull;

__device__ __forceinline__ ull pk(float a, float b) {
    ull r; asm("mov.b64 %0, {%1, %2};" : "=l"(r) : "f"(a), "f"(b)); return r;
}
__device__ __forceinline__ void upk(ull v, float& a, float& b) {
    asm("mov.b64 {%0, %1}, %2;" : "=f"(a), "=f"(b) : "l"(v));
}
__device__ __forceinline__ ull fma2(ull a, ull b, ull c) {
    ull d; asm("fma.rn.f32x2 %0, %1, %2, %3;" : "=l"(d) : "l"(a), "l"(b), "l"(c)); return d;
}
__device__ __forceinline__ float fex2(float x) {
    float e; asm("ex2.approx.f32 %0, %1;" : "=f"(e) : "f"(x)); return e;
}
__device__ __forceinline__ float frcp(float x) {
    float r; asm("rcp.approx.f32 %0, %1;" : "=f"(r) : "f"(x)); return r;
}
__device__ __forceinline__ void cp16(uint32_t dst, const void* src) {
    asm volatile("cp.async.ca.shared.global [%0], [%1], 16;" :: "r"(dst), "l"(src));
}

// 4 elements: q_i = 1/(exp2(acc_i)+1) with one shared rcp; dot q into d0v/d1v;
// then acc += xv*w1 (uses pre-update acc for q — site-d ordering).
__device__ __forceinline__ void process4(ull& a0, ull& a1,
                                         ull w1x, ull w1y,
                                         ull wxx, ull wxy,
                                         ull wyx, ull wyy,
                                         ull xv, ull& d0v, ull& d1v) {
    float s0, s1, s2, s3;
    upk(a0, s0, s1); upk(a1, s2, s3);
    const float e0 = fex2(s0), e1 = fex2(s1), e2 = fex2(s2), e3 = fex2(s3);
    const float u0 = e0 + 1.0f, u1 = e1 + 1.0f, u2 = e2 + 1.0f, u3 = e3 + 1.0f;
    const float b = u0 * u1;
    const float c = b * u2;
    const float p = c * u3;
    const float r  = frcp(p);
    const float q3 = r * c;
    const float r3 = r * u3;
    const float q2 = r3 * b;
    const float r2 = r3 * u2;          // 1/(u0*u1)
    const float q1 = r2 * u0;
    const float q0 = r2 * u1;
    const ull qv0 = pk(q0, q1);
    const ull qv1 = pk(q2, q3);
    d0v = fma2(qv0, wxx, d0v);  d0v = fma2(qv1, wxy, d0v);
    d1v = fma2(qv0, wyx, d1v);  d1v = fma2(qv1, wyy, d1v);
    a0 = fma2(xv, w1x, a0);
    a1 = fma2(xv, w1y, a1);
}

__global__ __launch_bounds__(THREADS, 2)
void qnade_kernel(const float* __restrict__ x,
                  const float* __restrict__ W1,
                  const float* __restrict__ b1,
                  const float* __restrict__ W2,
                  const float* __restrict__ b2,
                  float* __restrict__ out)
{
    // smem (floats): W1s[2][2*CH] (two rows per buffer) | W2xs[CH] | W2ys[CH]
    //              | Xs[256] | red[32] float4
    extern __shared__ float smem[];
    float*  W1s  = smem;                       // 2*2*CH = 18432
    float*  W2xs = smem + 4 * CH;              // 4608
    float*  W2ys = W2xs + CH;                  // 4608
    float*  Xs   = W2ys + CH;                  // 256
    float4* red  = (float4*)(Xs + B_SAMP * D_SITES);   // 32 float4

    const int t    = threadIdx.x;
    const int nl   = t >> 7;        // local sample 0..3
    const int hp   = t & 127;       // h-chunk 0..127 (32 h-values each)
    const int warp = t >> 5;
    const int lane = t & 31;
    const int n0   = blockIdx.x * B_SAMP;
    const uint32_t smem_u32 = (uint32_t)__cvta_generic_to_shared(smem);

    // ---- stage W2 (split, padded chunks) + spins ----
    const float2* W2g = (const float2*)W2;
    #pragma unroll
    for (int i = t; i < H_DIM; i += THREADS) {
        const float2 g = W2g[i];
        const int c = i >> 5, k = i & 31;
        W2xs[c * PAD_CH + k] = g.x;
        W2ys[c * PAD_CH + k] = g.y;
    }
    if (t < B_SAMP * D_SITES)
        Xs[t] = x[(size_t)n0 * D_SITES + t];

    // ---- stage W1 rows 0,1 into buffer 0 (2048 16B granules) ----
    #pragma unroll
    for (int j = t; j < 2 * H_DIM / 4; j += THREADS) {
        const int r = j >> 10, jr = j & 1023;
        cp16(smem_u32 + (uint32_t)(r * CH + (jr >> 3) * PAD_CH + ((jr & 7) << 2)) * 4u,
             W1 + 4 * j);
    }
    asm volatile("cp.async.commit_group;");

    // ---- acc init: pre-scaled b1 ----
    ull acc[16];
    {
        const float4* b1v = (const float4*)(b1 + hp * PER_THR);
        #pragma unroll
        for (int k = 0; k < 8; k++) {
            const float4 v = b1v[k];
            acc[2 * k]     = pk(KTANH * v.x, KTANH * v.y);
            acc[2 * k + 1] = pk(KTANH * v.z, KTANH * v.w);
        }
    }

    asm volatile("cp.async.wait_group 0;" ::: "memory");
    __syncthreads();   // W2/Xs/W1rows01 visible

    const float* WXb = W2xs + hp * PAD_CH;
    const float* WYb = W2ys + hp * PAD_CH;

    // ---- one-time C0/C1 = sum(W2 col) + b2 (needed by hp<2 threads) ----
    float C0 = 0.0f, C1 = 0.0f;
    {
        float sx = 0.0f, sy = 0.0f;
        const float4* wx4 = (const float4*)WXb;
        const float4* wy4 = (const float4*)WYb;
        #pragma unroll
        for (int k = 0; k < 8; k++) {
            const float4 a = wx4[k], bq = wy4[k];
            sx += (a.x + a.y) + (a.z + a.w);
            sy += (bq.x + bq.y) + (bq.z + bq.w);
        }
        #pragma unroll
        for (int o = 16; o; o >>= 1) {
            sx += __shfl_xor_sync(0xffffffffu, sx, o);
            sy += __shfl_xor_sync(0xffffffffu, sy, o);
        }
        if (lane == 0) red[16 + warp] = make_float4(sx, sy, 0.0f, 0.0f);
        __syncthreads();
        if (hp < 2) {
            float a0s = 0.0f, a1s = 0.0f;
            #pragma unroll
            for (int w = 0; w < 4; w++) {
                const float4 v = red[16 + nl * 4 + w];
                a0s += v.x; a1s += v.y;
            }
            C0 = a0s + b2[0];
            C1 = a1s + b2[1];
        }
    }

    float wav = 1.0f;
    int buf = 0;

    for (int p = 0; p < D_SITES / 2; p++) {
        // prefetch W1 rows 2p+2, 2p+3 into the other buffer
        if (p + 1 < D_SITES / 2) {
            const float* src = W1 + (size_t)(2 * p + 2) * H_DIM;
            const uint32_t dbase = smem_u32 + (uint32_t)((buf ^ 1) * 2 * CH) * 4u;
            #pragma unroll
            for (int j = t; j < 2 * H_DIM / 4; j += THREADS) {
                const int r = j >> 10, jr = j & 1023;
                cp16(dbase + (uint32_t)(r * CH + (jr >> 3) * PAD_CH + ((jr & 7) << 2)) * 4u,
                     src + 4 * j);
            }
        }
        asm volatile("cp.async.commit_group;");

        const float xsA = Xs[nl * D_SITES + 2 * p];
        const float xsB = Xs[nl * D_SITES + 2 * p + 1];
        const float cxA = KTANH * xsA, cxB = KTANH * xsB;
        const ull xvA = pk(cxA, cxA);
        const ull xvB = pk(cxB, cxB);

        const float* W1A = W1s + buf * 2 * CH + hp * PAD_CH;
        const float* W1B = W1A + CH;

        // ---- pass A: site 2p ----
        float D0a, D1a;
        {
            ull d0v = 0ull, d1v = 0ull;
            #pragma unroll
            for (int q = 0; q < 8; q++) {
                const ulonglong2 w1q = *(const ulonglong2*)(W1A + 4 * q);
                const ulonglong2 wxq = *(const ulonglong2*)(WXb + 4 * q);
                const ulonglong2 wyq = *(const ulonglong2*)(WYb + 4 * q);
                process4(acc[2 * q], acc[2 * q + 1],
                         w1q.x, w1q.y, wxq.x, wxq.y, wyq.x, wyq.y, xvA, d0v, d1v);
            }
            float a, b;
            upk(d0v, a, b); D0a = a + b;
            upk(d1v, a, b); D1a = a + b;
        }
        // start A's shuffle chain — overlaps with pass B compute
        #pragma unroll
        for (int o = 16; o; o >>= 1) {
            D0a += __shfl_xor_sync(0xffffffffu, D0a, o);
            D1a += __shfl_xor_sync(0xffffffffu, D1a, o);
        }

        // ---- pass B: site 2p+1 (acc now includes site 2p) ----
        float D0b, D1b;
        {
            ull d0v = 0ull, d1v = 0ull;
            #pragma unroll
            for (int q = 0; q < 8; q++) {
                const ulonglong2 w1q = *(const ulonglong2*)(W1B + 4 * q);
                const ulonglong2 wxq = *(const ulonglong2*)(WXb + 4 * q);
                const ulonglong2 wyq = *(const ulonglong2*)(WYb + 4 * q);
                process4(acc[2 * q], acc[2 * q + 1],
                         w1q.x, w1q.y, wxq.x, wxq.y, wyq.x, wyq.y, xvB, d0v, d1v);
            }
            float a, b;
            upk(d0v, a, b); D0b = a + b;
            upk(d1v, a, b); D1b = a + b;
        }
        #pragma unroll
        for (int o = 16; o; o >>= 1) {
            D0b += __shfl_xor_sync(0xffffffffu, D0b, o);
            D1b += __shfl_xor_sync(0xffffffffu, D1b, o);
        }

        if (lane == 0)
            red[(p & 1) * 16 + warp] = make_float4(D0a, D1a, D0b, D1b);

        asm volatile("cp.async.wait_group 0;" ::: "memory");
        __syncthreads();   // publishes red AND next W1 buffer

        // ---- leaders: hp==0 handles site 2p, hp==1 handles site 2p+1 ----
        if (hp < 2) {
            float S0 = 0.0f, S1 = 0.0f;
            #pragma unroll
            for (int w = 0; w < 4; w++) {
                const float4 v = red[(p & 1) * 16 + nl * 4 + w];
                S0 += hp ? v.z : v.x;
                S1 += hp ? v.w : v.y;
            }
            const float z0 = fmaf(-2.0f, S0, C0);
            const float z1 = fmaf(-2.0f, S1, C1);
            const float t0 = tanhf(z0), t1 = tanhf(z1);
            const float nrm = fmaxf(sqrtf(t0 * t0 + t1 * t1), 1e-12f);
            const float xs  = hp ? xsB : xsA;
            const float sel = (xs > 0.0f ? t0 : t1) / nrm;
            const float selB = __shfl_sync(0x3u, sel, 1);
            if (hp == 0) wav *= sel * selB;
        }
        buf ^= 1;
    }

    if (hp == 0) out[n0 + nl] = wav;
}

extern "C" void kernel_launch(void* const* d_in, const int* in_sizes, int n_in,
                              void* d_out, int out_size) {
    const float* x  = (const float*)d_in[0];   // [8192,64]
    const float* W1 = (const float*)d_in[1];   // [64,4096]
    const float* b1 = (const float*)d_in[2];   // [4096]
    const float* W2 = (const float*)d_in[3];   // [4096,2]
    const float* b2 = (const float*)d_in[4];   // [2]
    float* out = (float*)d_out;                // [8192]

    const int smem_bytes =
        (6 * CH + B_SAMP * D_SITES) * (int)sizeof(float) + 32 * (int)sizeof(float4);

    cudaFuncSetAttribute(qnade_kernel,
                         cudaFuncAttributeMaxDynamicSharedMemorySize, smem_bytes);

    qnade_kernel<<<N_SAMP / B_SAMP, THREADS, smem_bytes>>>(x, W1, b1, W2, b2, out);
}

// round 10
// speedup vs baseline: 3.9973x; 3.9973x over previous
#include <cuda_runtime.h>
#include <cstdint>

// QNADE — autoregressive NADE. N=8192, D=64, H=4096, M=2.
// R6 skeleton (1 site/iter, 1 sample/thread, no spills) + R7 algebra:
//   acc holds PRE-SCALED pre-activation: acc = 2*log2(e)*(b1 + sum_j x_j W1[j,:])
//   q = 1/(exp2(acc)+1)   (tanh = 1 - 2q), 4-way shared rcp
//   z = C - 2*dot(q, W2col),  C = sum(W2col) + b2   (computed once)

#define N_SAMP   8192
#define D_SITES  64
#define H_DIM    4096
#define B_SAMP   4
#define THREADS  512
#define HPART    128          // threads per sample
#define PER_THR  32           // h-elements per thread
#define PAD_CH   36           // 32 data + 4 pad words -> conflict-free LDS.128
#define CH       (HPART * PAD_CH)    // 4608 floats per W1 row buffer
#define KTANH    2.8853900817779268f // 2*log2(e)

typedef unsigned long long ull;

__device__ __forceinline__ ull pk(float a, float b) {
    ull r; asm("mov.b64 %0, {%1, %2};" : "=l"(r) : "f"(a), "f"(b)); return r;
}
__device__ __forceinline__ void upk(ull v, float& a, float& b) {
    asm("mov.b64 {%0, %1}, %2;" : "=f"(a), "=f"(b) : "l"(v));
}
__device__ __forceinline__ ull fma2(ull a, ull b, ull c) {
    ull d; asm("fma.rn.f32x2 %0, %1, %2, %3;" : "=l"(d) : "l"(a), "l"(b), "l"(c)); return d;
}
__device__ __forceinline__ float fex2(float x) {
    float e; asm("ex2.approx.f32 %0, %1;" : "=f"(e) : "f"(x)); return e;
}
__device__ __forceinline__ float frcp(float x) {
    float r; asm("rcp.approx.f32 %0, %1;" : "=f"(r) : "f"(x)); return r;
}
__device__ __forceinline__ void cp16(uint32_t dst, const void* src) {
    asm volatile("cp.async.ca.shared.global [%0], [%1], 16;" :: "r"(dst), "l"(src));
}

// 4 elements: q_i = 1/(exp2(acc_i)+1) with ONE rcp (prefix-suffix products);
// dot q into d0v/d1v; then acc += xv*w1 (q uses pre-update acc: site-d ordering).
__device__ __forceinline__ void process4(ull& a0, ull& a1,
                                         ull w1x, ull w1y,
                                         ull wxx, ull wxy,
                                         ull wyx, ull wyy,
                                         ull xv, ull& d0v, ull& d1v) {
    float s0, s1, s2, s3;
    upk(a0, s0, s1); upk(a1, s2, s3);
    const float e0 = fex2(s0), e1 = fex2(s1), e2 = fex2(s2), e3 = fex2(s3);
    const float u0 = e0 + 1.0f, u1 = e1 + 1.0f, u2 = e2 + 1.0f, u3 = e3 + 1.0f;
    const float b = u0 * u1;
    const float c = b * u2;
    const float p = c * u3;
    const float r  = frcp(p);
    const float q3 = r * c;
    const float r3 = r * u3;
    const float q2 = r3 * b;
    const float r2 = r3 * u2;          // 1/(u0*u1)
    const float q1 = r2 * u0;
    const float q0 = r2 * u1;
    const ull qv0 = pk(q0, q1);
    const ull qv1 = pk(q2, q3);
    d0v = fma2(qv0, wxx, d0v);  d0v = fma2(qv1, wxy, d0v);
    d1v = fma2(qv0, wyx, d1v);  d1v = fma2(qv1, wyy, d1v);
    a0 = fma2(xv, w1x, a0);
    a1 = fma2(xv, w1y, a1);
}

__global__ __launch_bounds__(THREADS, 2)
void qnade_kernel(const float* __restrict__ x,
                  const float* __restrict__ W1,
                  const float* __restrict__ b1,
                  const float* __restrict__ W2,
                  const float* __restrict__ b2,
                  float* __restrict__ out)
{
    // smem (floats): W1s[2][CH] | W2xs[CH] | W2ys[CH] | Xs[256] | red[2][16] float2
    extern __shared__ float smem[];
    float*  W1s  = smem;
    float*  W2xs = smem + 2 * CH;
    float*  W2ys = W2xs + CH;
    float*  Xs   = W2ys + CH;
    float2* red  = (float2*)(Xs + B_SAMP * D_SITES);

    const int t    = threadIdx.x;
    const int nl   = t >> 7;        // local sample 0..3
    const int hp   = t & 127;       // h-chunk 0..127 (32 h-values each)
    const int warp = t >> 5;
    const int lane = t & 31;
    const int n0   = blockIdx.x * B_SAMP;
    const bool leader = (hp == 0);
    const uint32_t smem_u32 = (uint32_t)__cvta_generic_to_shared(smem);

    // ---- stage W2 (split, chunk-padded) + spins ----
    const float2* W2g = (const float2*)W2;
    #pragma unroll
    for (int i = t; i < H_DIM; i += THREADS) {
        const float2 g = W2g[i];
        const int c = i >> 5, k = i & 31;
        W2xs[c * PAD_CH + k] = g.x;
        W2ys[c * PAD_CH + k] = g.y;
    }
    if (t < B_SAMP * D_SITES)
        Xs[t] = x[(size_t)n0 * D_SITES + t];

    // ---- stage W1 row 0 into buffer 0 ----
    #pragma unroll
    for (int j = t; j < H_DIM / 4; j += THREADS)
        cp16(smem_u32 + (uint32_t)((j >> 3) * PAD_CH + ((j & 7) << 2)) * 4u, W1 + 4 * j);
    asm volatile("cp.async.commit_group;");

    // ---- acc init: pre-scaled b1 ----
    ull acc[16];
    {
        const float4* b1v = (const float4*)(b1 + hp * PER_THR);
        #pragma unroll
        for (int k = 0; k < 8; k++) {
            const float4 v = b1v[k];
            acc[2 * k]     = pk(KTANH * v.x, KTANH * v.y);
            acc[2 * k + 1] = pk(KTANH * v.z, KTANH * v.w);
        }
    }

    asm volatile("cp.async.wait_group 0;" ::: "memory");
    __syncthreads();   // W2/Xs/W1row0 visible

    const float* WXb = W2xs + hp * PAD_CH;
    const float* WYb = W2ys + hp * PAD_CH;

    // ---- one-time C0/C1 = sum(W2 col) + b2 (leader threads only use it) ----
    float C0 = 0.0f, C1 = 0.0f;
    {
        float sx = 0.0f, sy = 0.0f;
        const float4* wx4 = (const float4*)WXb;
        const float4* wy4 = (const float4*)WYb;
        #pragma unroll
        for (int k = 0; k < 8; k++) {
            const float4 a = wx4[k], bq = wy4[k];
            sx += (a.x + a.y) + (a.z + a.w);
            sy += (bq.x + bq.y) + (bq.z + bq.w);
        }
        #pragma unroll
        for (int o = 16; o; o >>= 1) {
            sx += __shfl_xor_sync(0xffffffffu, sx, o);
            sy += __shfl_xor_sync(0xffffffffu, sy, o);
        }
        if (lane == 0) red[warp] = make_float2(sx, sy);
        __syncthreads();
        if (leader) {
            float a0s = 0.0f, a1s = 0.0f;
            #pragma unroll
            for (int w = 0; w < 4; w++) {
                const float2 v = red[nl * 4 + w];
                a0s += v.x; a1s += v.y;
            }
            C0 = a0s + b2[0];
            C1 = a1s + b2[1];
        }
        __syncthreads();   // red free for the main loop
    }

    float wav = 1.0f;
    int buf = 0;

    for (int d = 0; d < D_SITES; d++) {
        // prefetch W1 row d+1 into the other buffer
        if (d + 1 < D_SITES) {
            const float* src = W1 + (size_t)(d + 1) * H_DIM;
            const uint32_t dbase = smem_u32 + (uint32_t)((buf ^ 1) * CH) * 4u;
            #pragma unroll
            for (int j = t; j < H_DIM / 4; j += THREADS)
                cp16(dbase + (uint32_t)((j >> 3) * PAD_CH + ((j & 7) << 2)) * 4u, src + 4 * j);
        }
        asm volatile("cp.async.commit_group;");

        const float xs = Xs[nl * D_SITES + d];
        const float cx = KTANH * xs;
        const ull xv = pk(cx, cx);
        const float* W1b = W1s + buf * CH + hp * PAD_CH;

        ull d0v = 0ull, d1v = 0ull;
        #pragma unroll
        for (int q = 0; q < 8; q++) {
            const ulonglong2 w1q = *(const ulonglong2*)(W1b + 4 * q);
            const ulonglong2 wxq = *(const ulonglong2*)(WXb + 4 * q);
            const ulonglong2 wyq = *(const ulonglong2*)(WYb + 4 * q);
            process4(acc[2 * q], acc[2 * q + 1],
                     w1q.x, w1q.y, wxq.x, wxq.y, wyq.x, wyq.y, xv, d0v, d1v);
        }
        float a, b;
        upk(d0v, a, b); float D0 = a + b;
        upk(d1v, a, b); float D1 = a + b;

        #pragma unroll
        for (int o = 16; o; o >>= 1) {
            D0 += __shfl_xor_sync(0xffffffffu, D0, o);
            D1 += __shfl_xor_sync(0xffffffffu, D1, o);
        }
        float2* redb = red + (d & 1) * 16;
        if (lane == 0) redb[warp] = make_float2(D0, D1);

        asm volatile("cp.async.wait_group 0;" ::: "memory");
        __syncthreads();   // publishes red AND next W1 buffer

        if (leader) {
            const float2 r0 = redb[nl * 4 + 0];
            const float2 r1 = redb[nl * 4 + 1];
            const float2 r2 = redb[nl * 4 + 2];
            const float2 r3 = redb[nl * 4 + 3];
            const float S0 = (r0.x + r1.x) + (r2.x + r3.x);
            const float S1 = (r0.y + r1.y) + (r2.y + r3.y);
            const float z0 = fmaf(-2.0f, S0, C0);
            const float z1 = fmaf(-2.0f, S1, C1);
            const float t0 = tanhf(z0), t1 = tanhf(z1);
            const float nrm = fmaxf(sqrtf(t0 * t0 + t1 * t1), 1e-12f);
            wav *= (xs > 0.0f ? t0 : t1) / nrm;
        }
        buf ^= 1;
    }

    if (leader) out[n0 + nl] = wav;
}

extern "C" void kernel_launch(void* const* d_in, const int* in_sizes, int n_in,
                              void* d_out, int out_size) {
    const float* x  = (const float*)d_in[0];   // [8192,64]
    const float* W1 = (const float*)d_in[1];   // [64,4096]
    const float* b1 = (const float*)d_in[2];   // [4096]
    const float* W2 = (const float*)d_in[3];   // [4096,2]
    const float* b2 = (const float*)d_in[4];   // [2]
    float* out = (float*)d_out;                // [8192]

    const int smem_bytes =
        (4 * CH + B_SAMP * D_SITES) * (int)sizeof(float) + 32 * (int)sizeof(float2);

    cudaFuncSetAttribute(qnade_kernel,
                         cudaFuncAttributeMaxDynamicSharedMemorySize, smem_bytes);

    qnade_kernel<<<N_SAMP / B_SAMP, THREADS, smem_bytes>>>(x, W1, b1, W2, b2, out);
}